// round 12
// baseline (speedup 1.0000x reference)
#include <cuda_runtime.h>
#include <cuda.h>

typedef unsigned long long ull;

// out = (w1+w2)*s + (w3-w2)*G3(s) + (w4-w3)*G5(s) - w4*G7(s)
// Per-warp independent streaming pipelines: block = 4 warps, each warp owns a
// 128x128 strip, its own 3-stage smem ring, its own mbarriers, and issues its
// own TMA chunks (lane 0). NO block-wide syncs after init -> decorrelated DRAM
// demand. Horizontal: 3x LDS.128 + FFMA-imm. Vertical: transposed-FIR f32x2,
// 8-slot ring.

#define IMG 512
#define NTH 128
#define SW 136              // strip width + halo (128 + 4 + 4)
#define CH 8                // chunk rows
#define NST 3               // pipeline stages per warp
#define NCHUNK 17           // 136 rows >= 134 needed
#define STRIP_CHUNK_BYTES (CH * SW * 4)   // 4352 per warp-chunk

#define K3_0 0.5220116f
#define K3_1 0.2389942f
#define K5_0 0.3695467f
#define K5_1 0.2444604f
#define K5_2 0.0707663f
#define K7_0 0.2880262f
#define K7_1 0.2231734f
#define K7_2 0.1038183f
#define K7_3 0.0289952f

__device__ __forceinline__ ull pk2(float lo, float hi) {
    ull r; asm("mov.b64 %0, {%1, %2};" : "=l"(r) : "f"(lo), "f"(hi)); return r;
}
__device__ __forceinline__ ull mul2(ull a, ull b) {
    ull r; asm("mul.rn.f32x2 %0, %1, %2;" : "=l"(r) : "l"(a), "l"(b)); return r;
}
__device__ __forceinline__ ull fma2(ull a, ull b, ull c) {
    ull r; asm("fma.rn.f32x2 %0, %1, %2, %3;" : "=l"(r) : "l"(a), "l"(b), "l"(c)); return r;
}
__device__ __forceinline__ unsigned smem_u32(const void* p) {
    unsigned r;
    asm("{ .reg .u64 t; cvta.to.shared.u64 t, %1; cvt.u32.u64 %0, t; }" : "=r"(r) : "l"(p));
    return r;
}
__device__ __forceinline__ void mbar_wait(unsigned mb, unsigned parity) {
    unsigned done;
    asm volatile(
        "{\n\t.reg .pred p;\n\t"
        "mbarrier.try_wait.parity.acquire.cta.shared::cta.b64 p, [%1], %2;\n\t"
        "selp.b32 %0, 1, 0, p;\n\t}"
        : "=r"(done) : "r"(mb), "r"(parity) : "memory");
    if (!done) {
        asm volatile(
            "{\n\t.reg .pred P1;\n\t"
            "W%=:\n\t"
            "mbarrier.try_wait.parity.acquire.cta.shared::cta.b64 P1, [%0], %1, 0x989680;\n\t"
            "@P1 bra.uni D%=;\n\t"
            "bra.uni W%=;\n\t"
            "D%=:\n\t}"
            :: "r"(mb), "r"(parity) : "memory");
    }
}

// ---- per-warp streaming TMA kernel ----
__global__ void __launch_bounds__(NTH, 4)
mgdf_tma_stream(const __grid_constant__ CUtensorMap tmap,
                const float* __restrict__ w1p, const float* __restrict__ w2p,
                const float* __restrict__ w3p, const float* __restrict__ w4p,
                float* __restrict__ out)
{
    // sm[warp][stage][row][col]; mbar[warp][stage]
    __shared__ __align__(128) float sm[4][NST][CH][SW];
    __shared__ __align__(8) ull mbar[4][NST];

    const int tid  = threadIdx.x;
    const int lane = tid & 31;
    const int st_w = tid >> 5;                 // warp = strip 0..3
    const int band = blockIdx.x;               // 0..3 row bands of 128
    const int img  = blockIdx.y;
    const int y0   = band * 128 - 3;           // first input row (top halo)
    const int sx   = st_w * 128 - 4;           // strip's TMA x origin

    float* orow = out + (size_t)img * (IMG * IMG)
                      + (size_t)(band * 128) * IMG + st_w * 128 + 4 * lane;

    const unsigned mbw = smem_u32(&mbar[st_w][0]);   // this warp's 3 barriers
    if (tid < 4 * NST) {
        asm volatile("mbarrier.init.shared.b64 [%0], 1;"
                     :: "r"(smem_u32(&mbar[0][0]) + 8u * tid) : "memory");
    }
    __syncthreads();   // the ONLY block-wide sync (barrier init visibility)

    // issue this warp's chunk n into stage st (lane 0 only)
    #define ISSUE(n, st)                                                         \
    if (lane == 0) {                                                             \
        unsigned mbx = mbw + 8u * (st);                                          \
        asm volatile("mbarrier.arrive.expect_tx.shared.b64 _, [%0], %1;"         \
                     :: "r"(mbx), "r"((unsigned)STRIP_CHUNK_BYTES) : "memory");  \
        asm volatile(                                                            \
            "cp.async.bulk.tensor.3d.shared::cta.global.tile"                    \
            ".mbarrier::complete_tx::bytes [%0], [%1, {%2, %3, %4}], [%5];"      \
            :: "r"(smem_u32(&sm[st_w][st][0][0])), "l"(&tmap),                   \
               "r"(sx), "r"(y0 + (n) * CH), "r"(img), "r"(mbx)                   \
            : "memory");                                                         \
    }

    ISSUE(0, 0) ISSUE(1, 1) ISSUE(2, 2)

    // weights folded into vertical coefficients
    const float W1 = *w1p, W2 = *w2p, W3 = *w3p, W4 = *w4p;
    const float cA = W1 + W2, cB = W3 - W2, cC = W4 - W3, cD = -W4;
    const ull cAp = pk2(cA, cA);
    const ull a30 = pk2(cB * K3_0, cB * K3_0);
    const ull a31 = pk2(cB * K3_1, cB * K3_1);
    const ull a50 = pk2(cC * K5_0, cC * K5_0);
    const ull a51 = pk2(cC * K5_1, cC * K5_1);
    const ull a52 = pk2(cC * K5_2, cC * K5_2);
    const ull a70 = pk2(cD * K7_0, cD * K7_0);
    const ull a71 = pk2(cD * K7_1, cD * K7_1);
    const ull a72 = pk2(cD * K7_2, cD * K7_2);
    const ull a73 = pk2(cD * K7_3, cD * K7_3);

    const int cb = 4 * lane;       // smem col of first tap float4; centers cb+4..cb+7
    ull acc[8][2];

    // One step: row J of current chunk (J literal 0..7; k%8 == J).
    #define STEP(BP, J, D0, D1, D2, D3, D4, D5, D6)                              \
    {                                                                            \
        const float* rp = (BP) + (J) * SW + cb;                                  \
        float4 A  = *reinterpret_cast<const float4*>(rp);                        \
        float4 Bv = *reinterpret_cast<const float4*>(rp + 4);                    \
        float4 C  = *reinterpret_cast<const float4*>(rp + 8);                    \
        float x1 = A.y, x2 = A.z, x3 = A.w;                                      \
        float x4 = Bv.x, x5 = Bv.y, x6 = Bv.z, x7 = Bv.w;                        \
        float x8 = C.x, x9 = C.y, x10 = C.z;                                     \
        float h3v[4], h5v[4], h7v[4];                                            \
        {                                                                        \
            float p1, p2, p3;                                                    \
            p1 = x3 + x5;  p2 = x2 + x6;  p3 = x1 + x7;                          \
            h3v[0] = K3_0 * x4 + K3_1 * p1;                                      \
            h5v[0] = K5_0 * x4 + K5_1 * p1 + K5_2 * p2;                          \
            h7v[0] = K7_0 * x4 + K7_1 * p1 + K7_2 * p2 + K7_3 * p3;              \
            p1 = x4 + x6;  p2 = x3 + x7;  p3 = x2 + x8;                          \
            h3v[1] = K3_0 * x5 + K3_1 * p1;                                      \
            h5v[1] = K5_0 * x5 + K5_1 * p1 + K5_2 * p2;                          \
            h7v[1] = K7_0 * x5 + K7_1 * p1 + K7_2 * p2 + K7_3 * p3;              \
            p1 = x5 + x7;  p2 = x4 + x8;  p3 = x3 + x9;                          \
            h3v[2] = K3_0 * x6 + K3_1 * p1;                                      \
            h5v[2] = K5_0 * x6 + K5_1 * p1 + K5_2 * p2;                          \
            h7v[2] = K7_0 * x6 + K7_1 * p1 + K7_2 * p2 + K7_3 * p3;              \
            p1 = x6 + x8;  p2 = x5 + x9;  p3 = x4 + x10;                         \
            h3v[3] = K3_0 * x7 + K3_1 * p1;                                      \
            h5v[3] = K5_0 * x7 + K5_1 * p1 + K5_2 * p2;                          \
            h7v[3] = K7_0 * x7 + K7_1 * p1 + K7_2 * p2 + K7_3 * p3;              \
        }                                                                        \
        ull t3a = pk2(h3v[0], h3v[1]), t3b = pk2(h3v[2], h3v[3]);                \
        ull t5a = pk2(h5v[0], h5v[1]), t5b = pk2(h5v[2], h5v[3]);                \
        ull t7a = pk2(h7v[0], h7v[1]), t7b = pk2(h7v[2], h7v[3]);                \
        ull rwa = pk2(x4, x5),          rwb = pk2(x6, x7);                       \
        if (D0) {                                                                \
            acc[(J) & 7][0] = mul2(a73, t7a);                                    \
            acc[(J) & 7][1] = mul2(a73, t7b);                                    \
        }                                                                        \
        if (D1) {                                                                \
            const int sl = ((J) - 1) & 7;                                        \
            ull u = acc[sl][0], v = acc[sl][1];                                  \
            u = fma2(a72, t7a, u);  v = fma2(a72, t7b, v);                       \
            u = fma2(a52, t5a, u);  v = fma2(a52, t5b, v);                       \
            acc[sl][0] = u; acc[sl][1] = v;                                      \
        }                                                                        \
        if (D2) {                                                                \
            const int sl = ((J) - 2) & 7;                                        \
            ull u = acc[sl][0], v = acc[sl][1];                                  \
            u = fma2(a71, t7a, u);  v = fma2(a71, t7b, v);                       \
            u = fma2(a51, t5a, u);  v = fma2(a51, t5b, v);                       \
            u = fma2(a31, t3a, u);  v = fma2(a31, t3b, v);                       \
            acc[sl][0] = u; acc[sl][1] = v;                                      \
        }                                                                        \
        if (D3) {                                                                \
            const int sl = ((J) - 3) & 7;                                        \
            ull u = acc[sl][0], v = acc[sl][1];                                  \
            u = fma2(a70, t7a, u);  v = fma2(a70, t7b, v);                       \
            u = fma2(a50, t5a, u);  v = fma2(a50, t5b, v);                       \
            u = fma2(a30, t3a, u);  v = fma2(a30, t3b, v);                       \
            u = fma2(cAp, rwa, u);  v = fma2(cAp, rwb, v);                       \
            acc[sl][0] = u; acc[sl][1] = v;                                      \
        }                                                                        \
        if (D4) {                                                                \
            const int sl = ((J) - 4) & 7;                                        \
            ull u = acc[sl][0], v = acc[sl][1];                                  \
            u = fma2(a71, t7a, u);  v = fma2(a71, t7b, v);                       \
            u = fma2(a51, t5a, u);  v = fma2(a51, t5b, v);                       \
            u = fma2(a31, t3a, u);  v = fma2(a31, t3b, v);                       \
            acc[sl][0] = u; acc[sl][1] = v;                                      \
        }                                                                        \
        if (D5) {                                                                \
            const int sl = ((J) - 5) & 7;                                        \
            ull u = acc[sl][0], v = acc[sl][1];                                  \
            u = fma2(a72, t7a, u);  v = fma2(a72, t7b, v);                       \
            u = fma2(a52, t5a, u);  v = fma2(a52, t5b, v);                       \
            acc[sl][0] = u; acc[sl][1] = v;                                      \
        }                                                                        \
        if (D6) {                                                                \
            const int sl = ((J) - 6) & 7;                                        \
            ulonglong2 o;                                                        \
            o.x = fma2(a73, t7a, acc[sl][0]);                                    \
            o.y = fma2(a73, t7b, acc[sl][1]);                                    \
            *reinterpret_cast<ulonglong2*>(orow) = o;                            \
            orow += IMG;                                                         \
        }                                                                        \
    }

    // ---- chunk 0 (k = 0..7): guards k >= d ----
    mbar_wait(mbw, 0);
    {
        const float* bp = &sm[st_w][0][0][0];
        STEP(bp, 0, 1,0,0,0,0,0,0)
        STEP(bp, 1, 1,1,0,0,0,0,0)
        STEP(bp, 2, 1,1,1,0,0,0,0)
        STEP(bp, 3, 1,1,1,1,0,0,0)
        STEP(bp, 4, 1,1,1,1,1,0,0)
        STEP(bp, 5, 1,1,1,1,1,1,0)
        STEP(bp, 6, 1,1,1,1,1,1,1)
        STEP(bp, 7, 1,1,1,1,1,1,1)
    }
    ISSUE(3, 0)

    // ---- chunks 1..15 (k = 8..127): fully unconditional, per-warp pipeline ----
    #pragma unroll 1
    for (int c = 1; c <= 15; c++) {
        const int st = c % 3;
        mbar_wait(mbw + 8u * st, (unsigned)((c / 3) & 1));
        const float* bp = &sm[st_w][st][0][0];
        STEP(bp, 0, 1,1,1,1,1,1,1)
        STEP(bp, 1, 1,1,1,1,1,1,1)
        STEP(bp, 2, 1,1,1,1,1,1,1)
        STEP(bp, 3, 1,1,1,1,1,1,1)
        STEP(bp, 4, 1,1,1,1,1,1,1)
        STEP(bp, 5, 1,1,1,1,1,1,1)
        STEP(bp, 6, 1,1,1,1,1,1,1)
        STEP(bp, 7, 1,1,1,1,1,1,1)
        if (c + 3 <= NCHUNK - 1) ISSUE(c + 3, st)
    }

    // ---- chunk 16 (k = 128..133): tail guards ----
    mbar_wait(mbw + 8u * (16 % 3), (unsigned)((16 / 3) & 1));
    {
        const float* bp = &sm[st_w][16 % 3][0][0];
        STEP(bp, 0, 0,1,1,1,1,1,1)
        STEP(bp, 1, 0,0,1,1,1,1,1)
        STEP(bp, 2, 0,0,0,1,1,1,1)
        STEP(bp, 3, 0,0,0,0,1,1,1)
        STEP(bp, 4, 0,0,0,0,0,1,1)
        STEP(bp, 5, 0,0,0,0,0,0,1)
    }
    #undef STEP
    #undef ISSUE
}

// ---- fallback kernel (TMA encode unavailable): R10 LDG tile version ----
#define FTX 128
#define FTY 128
#define FNTH 256
#define FSH 134
#define FNF4 (SW / 4)

__global__ void __launch_bounds__(FNTH, 3)
mgdf_ldg_kernel(const float* __restrict__ s,
                const float* __restrict__ w1p, const float* __restrict__ w2p,
                const float* __restrict__ w3p, const float* __restrict__ w4p,
                float* __restrict__ out)
{
    __shared__ __align__(16) float tile[FSH][SW];

    const int img = blockIdx.z;
    const size_t base = (size_t)img * (IMG * IMG);
    const float* sp = s + base;
    float* op = out + base;
    const int tileX = blockIdx.x * FTX;
    const int tileY = blockIdx.y * FTY;
    const int tid = threadIdx.x;

    #pragma unroll
    for (int idx = tid; idx < FSH * FNF4; idx += FNTH) {
        int r = idx / FNF4;
        int c4 = idx - r * FNF4;
        int gy = tileY - 3 + r;
        int gx = tileX - 4 + c4 * 4;
        float4 v = make_float4(0.f, 0.f, 0.f, 0.f);
        if ((unsigned)gy < (unsigned)IMG && (unsigned)gx < (unsigned)IMG)
            v = *reinterpret_cast<const float4*>(sp + gy * IMG + gx);
        *reinterpret_cast<float4*>(&tile[r][c4 * 4]) = v;
    }
    __syncthreads();

    const float W1 = *w1p, W2 = *w2p, W3 = *w3p, W4 = *w4p;
    const float cA = W1 + W2, cB = W3 - W2, cC = W4 - W3, cD = -W4;
    const ull cAp = pk2(cA, cA);
    const ull a30 = pk2(cB * K3_0, cB * K3_0);
    const ull a31 = pk2(cB * K3_1, cB * K3_1);
    const ull a50 = pk2(cC * K5_0, cC * K5_0);
    const ull a51 = pk2(cC * K5_1, cC * K5_1);
    const ull a52 = pk2(cC * K5_2, cC * K5_2);
    const ull a70 = pk2(cD * K7_0, cD * K7_0);
    const ull a71 = pk2(cD * K7_1, cD * K7_1);
    const ull a72 = pk2(cD * K7_2, cD * K7_2);
    const ull a73 = pk2(cD * K7_3, cD * K7_3);

    const int xg = tid & 31;
    const int rg = tid >> 5;
    const int cb = 4 * xg;
    const int rowBase = rg * 16;
    float* orow = op + (size_t)(tileY + rowBase) * IMG + tileX + 4 * xg;

    ull acc[7][2];

    #pragma unroll
    for (int k = 0; k < 22; k++) {
        const int sr = rowBase + k;
        float4 A = *reinterpret_cast<const float4*>(&tile[sr][cb]);
        float4 Bv = *reinterpret_cast<const float4*>(&tile[sr][cb + 4]);
        float4 C = *reinterpret_cast<const float4*>(&tile[sr][cb + 8]);
        float x1 = A.y, x2 = A.z, x3 = A.w;
        float x4 = Bv.x, x5 = Bv.y, x6 = Bv.z, x7 = Bv.w;
        float x8 = C.x, x9 = C.y, x10 = C.z;

        float h3v[4], h5v[4], h7v[4];
        {
            float p1, p2, p3;
            p1 = x3 + x5;  p2 = x2 + x6;  p3 = x1 + x7;
            h3v[0] = K3_0 * x4 + K3_1 * p1;
            h5v[0] = K5_0 * x4 + K5_1 * p1 + K5_2 * p2;
            h7v[0] = K7_0 * x4 + K7_1 * p1 + K7_2 * p2 + K7_3 * p3;
            p1 = x4 + x6;  p2 = x3 + x7;  p3 = x2 + x8;
            h3v[1] = K3_0 * x5 + K3_1 * p1;
            h5v[1] = K5_0 * x5 + K5_1 * p1 + K5_2 * p2;
            h7v[1] = K7_0 * x5 + K7_1 * p1 + K7_2 * p2 + K7_3 * p3;
            p1 = x5 + x7;  p2 = x4 + x8;  p3 = x3 + x9;
            h3v[2] = K3_0 * x6 + K3_1 * p1;
            h5v[2] = K5_0 * x6 + K5_1 * p1 + K5_2 * p2;
            h7v[2] = K7_0 * x6 + K7_1 * p1 + K7_2 * p2 + K7_3 * p3;
            p1 = x6 + x8;  p2 = x5 + x9;  p3 = x4 + x10;
            h3v[3] = K3_0 * x7 + K3_1 * p1;
            h5v[3] = K5_0 * x7 + K5_1 * p1 + K5_2 * p2;
            h7v[3] = K7_0 * x7 + K7_1 * p1 + K7_2 * p2 + K7_3 * p3;
        }
        ull t3a = pk2(h3v[0], h3v[1]), t3b = pk2(h3v[2], h3v[3]);
        ull t5a = pk2(h5v[0], h5v[1]), t5b = pk2(h5v[2], h5v[3]);
        ull t7a = pk2(h7v[0], h7v[1]), t7b = pk2(h7v[2], h7v[3]);
        ull rwa = pk2(x4, x5),          rwb = pk2(x6, x7);

        if (k <= 15) {
            acc[k % 7][0] = mul2(a73, t7a);
            acc[k % 7][1] = mul2(a73, t7b);
        }
        if (k >= 1 && k <= 16) {
            ull u = acc[(k - 1) % 7][0], v = acc[(k - 1) % 7][1];
            u = fma2(a72, t7a, u);  v = fma2(a72, t7b, v);
            u = fma2(a52, t5a, u);  v = fma2(a52, t5b, v);
            acc[(k - 1) % 7][0] = u; acc[(k - 1) % 7][1] = v;
        }
        if (k >= 2 && k <= 17) {
            ull u = acc[(k - 2) % 7][0], v = acc[(k - 2) % 7][1];
            u = fma2(a71, t7a, u);  v = fma2(a71, t7b, v);
            u = fma2(a51, t5a, u);  v = fma2(a51, t5b, v);
            u = fma2(a31, t3a, u);  v = fma2(a31, t3b, v);
            acc[(k - 2) % 7][0] = u; acc[(k - 2) % 7][1] = v;
        }
        if (k >= 3 && k <= 18) {
            ull u = acc[(k - 3) % 7][0], v = acc[(k - 3) % 7][1];
            u = fma2(a70, t7a, u);  v = fma2(a70, t7b, v);
            u = fma2(a50, t5a, u);  v = fma2(a50, t5b, v);
            u = fma2(a30, t3a, u);  v = fma2(a30, t3b, v);
            u = fma2(cAp, rwa, u);  v = fma2(cAp, rwb, v);
            acc[(k - 3) % 7][0] = u; acc[(k - 3) % 7][1] = v;
        }
        if (k >= 4 && k <= 19) {
            ull u = acc[(k - 4) % 7][0], v = acc[(k - 4) % 7][1];
            u = fma2(a71, t7a, u);  v = fma2(a71, t7b, v);
            u = fma2(a51, t5a, u);  v = fma2(a51, t5b, v);
            u = fma2(a31, t3a, u);  v = fma2(a31, t3b, v);
            acc[(k - 4) % 7][0] = u; acc[(k - 4) % 7][1] = v;
        }
        if (k >= 5 && k <= 20) {
            ull u = acc[(k - 5) % 7][0], v = acc[(k - 5) % 7][1];
            u = fma2(a72, t7a, u);  v = fma2(a72, t7b, v);
            u = fma2(a52, t5a, u);  v = fma2(a52, t5b, v);
            acc[(k - 5) % 7][0] = u; acc[(k - 5) % 7][1] = v;
        }
        if (k >= 6) {
            ulonglong2 o;
            o.x = fma2(a73, t7a, acc[(k - 6) % 7][0]);
            o.y = fma2(a73, t7b, acc[(k - 6) % 7][1]);
            *reinterpret_cast<ulonglong2*>(orow + (size_t)(k - 6) * IMG) = o;
        }
    }
}

typedef CUresult (*PFN_tmapEncode)(
    CUtensorMap*, CUtensorMapDataType, cuuint32_t, void*,
    const cuuint64_t*, const cuuint64_t*, const cuuint32_t*, const cuuint32_t*,
    CUtensorMapInterleave, CUtensorMapSwizzle, CUtensorMapL2promotion,
    CUtensorMapFloatOOBfill);

extern "C" void kernel_launch(void* const* d_in, const int* in_sizes, int n_in,
                              void* d_out, int out_size)
{
    const float* s  = (const float*)d_in[0];
    const float* w1 = (const float*)d_in[1];
    const float* w2 = (const float*)d_in[2];
    const float* w3 = (const float*)d_in[3];
    const float* w4 = (const float*)d_in[4];
    float* out = (float*)d_out;

    const int n_img = in_sizes[0] / (IMG * IMG);       // 192

    static PFN_tmapEncode pfn = nullptr;
    static bool resolved = false;
    if (!resolved) {
        void* fp = nullptr;
        cudaDriverEntryPointQueryResult qr = cudaDriverEntryPointSymbolNotFound;
        if (cudaGetDriverEntryPointByVersion("cuTensorMapEncodeTiled", &fp, 12000,
                                             cudaEnableDefault, &qr) == cudaSuccess &&
            qr == cudaDriverEntryPointSuccess)
            pfn = (PFN_tmapEncode)fp;
        resolved = true;
    }

    CUtensorMap tmap;
    bool use_tma = false;
    if (pfn) {
        cuuint64_t dims[3]    = {IMG, IMG, (cuuint64_t)n_img};
        cuuint64_t strides[2] = {IMG * 4ull, (cuuint64_t)IMG * IMG * 4ull};
        cuuint32_t box[3]     = {SW, CH, 1};
        cuuint32_t estr[3]    = {1, 1, 1};
        use_tma = (pfn(&tmap, CU_TENSOR_MAP_DATA_TYPE_FLOAT32, 3, (void*)s,
                       dims, strides, box, estr,
                       CU_TENSOR_MAP_INTERLEAVE_NONE, CU_TENSOR_MAP_SWIZZLE_NONE,
                       CU_TENSOR_MAP_L2_PROMOTION_L2_128B,
                       CU_TENSOR_MAP_FLOAT_OOB_FILL_NONE) == CUDA_SUCCESS);
    }

    if (use_tma) {
        dim3 grid(4, n_img);                            // 768 blocks, 128 threads
        mgdf_tma_stream<<<grid, NTH>>>(tmap, w1, w2, w3, w4, out);
    } else {
        dim3 grid(IMG / FTX, IMG / FTY, n_img);         // (4, 4, 192)
        mgdf_ldg_kernel<<<grid, FNTH>>>(s, w1, w2, w3, w4, out);
    }
}

// round 14
// speedup vs baseline: 1.0998x; 1.0998x over previous
#include <cuda_runtime.h>
#include <cuda.h>

typedef unsigned long long ull;

// out = (w1+w2)*s + (w3-w2)*G3(s) + (w4-w3)*G5(s) - w4*G7(s)
// R10 skeleton (tile 128x128, 4 cols/thread via 3x LDS.128, FFMA-imm horizontal,
// transposed-FIR f32x2 vertical ring, 3 CTAs/SM) with:
//   - quarter-split TMA fill at 128B-ALIGNED row offsets {0,36,72,108}
//     (row stride 544B; offset*544 % 128 == 0 iff row % 4 == 0)
//   - per-warp mbarrier waits: each warp waits only on quarters covering its rows
//   - streaming stores (st.global.cs): keep never-re-read output out of L2

#define IMG 512
#define TX 128
#define TY 128
#define NTH 256
#define SW 136            // TX + 8 (left halo 4, right halo 4)
#define SH 134            // TY + 6
#define NF4 (SW / 4)
#define STEPS 22
#define QAROWS 36         // quarters 0..2
#define QBROWS 26         // quarter 3
#define QABYTES (QAROWS * SW * 4)   // 19584
#define QBBYTES (QBROWS * SW * 4)   // 14144

#define K3_0 0.5220116f
#define K3_1 0.2389942f
#define K5_0 0.3695467f
#define K5_1 0.2444604f
#define K5_2 0.0707663f
#define K7_0 0.2880262f
#define K7_1 0.2231734f
#define K7_2 0.1038183f
#define K7_3 0.0289952f

__device__ __forceinline__ ull pk2(float lo, float hi) {
    ull r; asm("mov.b64 %0, {%1, %2};" : "=l"(r) : "f"(lo), "f"(hi)); return r;
}
__device__ __forceinline__ ull mul2(ull a, ull b) {
    ull r; asm("mul.rn.f32x2 %0, %1, %2;" : "=l"(r) : "l"(a), "l"(b)); return r;
}
__device__ __forceinline__ ull fma2(ull a, ull b, ull c) {
    ull r; asm("fma.rn.f32x2 %0, %1, %2, %3;" : "=l"(r) : "l"(a), "l"(b), "l"(c)); return r;
}
__device__ __forceinline__ unsigned smem_u32(const void* p) {
    unsigned r;
    asm("{ .reg .u64 t; cvta.to.shared.u64 t, %1; cvt.u32.u64 %0, t; }" : "=r"(r) : "l"(p));
    return r;
}
__device__ __forceinline__ void mbar_wait(unsigned mb, unsigned parity) {
    unsigned done;
    asm volatile(
        "{\n\t.reg .pred p;\n\t"
        "mbarrier.try_wait.parity.acquire.cta.shared::cta.b64 p, [%1], %2;\n\t"
        "selp.b32 %0, 1, 0, p;\n\t}"
        : "=r"(done) : "r"(mb), "r"(parity) : "memory");
    if (!done) {
        asm volatile(
            "{\n\t.reg .pred P1;\n\t"
            "W%=:\n\t"
            "mbarrier.try_wait.parity.acquire.cta.shared::cta.b64 P1, [%0], %1, 0x989680;\n\t"
            "@P1 bra.uni D%=;\n\t"
            "bra.uni W%=;\n\t"
            "D%=:\n\t}"
            :: "r"(mb), "r"(parity) : "memory");
    }
}

// ---- compute body: 4 cols/thread, 3x LDS.128 horizontal, f32x2 ring vertical ----
__device__ __forceinline__ void compute_tile(
    float (&tile)[SH][SW],
    const float* __restrict__ w1p, const float* __restrict__ w2p,
    const float* __restrict__ w3p, const float* __restrict__ w4p,
    float* __restrict__ op, int tileX, int tileY)
{
    const int tid = threadIdx.x;
    const float W1 = *w1p, W2 = *w2p, W3 = *w3p, W4 = *w4p;
    const float cA = W1 + W2, cB = W3 - W2, cC = W4 - W3, cD = -W4;
    const ull cAp = pk2(cA, cA);
    const ull a30 = pk2(cB * K3_0, cB * K3_0);
    const ull a31 = pk2(cB * K3_1, cB * K3_1);
    const ull a50 = pk2(cC * K5_0, cC * K5_0);
    const ull a51 = pk2(cC * K5_1, cC * K5_1);
    const ull a52 = pk2(cC * K5_2, cC * K5_2);
    const ull a70 = pk2(cD * K7_0, cD * K7_0);
    const ull a71 = pk2(cD * K7_1, cD * K7_1);
    const ull a72 = pk2(cD * K7_2, cD * K7_2);
    const ull a73 = pk2(cD * K7_3, cD * K7_3);

    const int xg = tid & 31;            // 32 col-groups of 4 cols
    const int rg = tid >> 5;            // 8 row-groups (== warp id)
    const int cb = 4 * xg;              // first float4; centers cb+4..cb+7
    const int rowBase = rg * 16;
    float* orow = op + (size_t)(tileY + rowBase) * IMG + tileX + 4 * xg;

    ull acc[7][2];

    #pragma unroll
    for (int k = 0; k < STEPS; k++) {
        const int sr = rowBase + k;

        float4 A = *reinterpret_cast<const float4*>(&tile[sr][cb]);
        float4 Bv = *reinterpret_cast<const float4*>(&tile[sr][cb + 4]);
        float4 C = *reinterpret_cast<const float4*>(&tile[sr][cb + 8]);
        float x1 = A.y, x2 = A.z, x3 = A.w;
        float x4 = Bv.x, x5 = Bv.y, x6 = Bv.z, x7 = Bv.w;
        float x8 = C.x, x9 = C.y, x10 = C.z;

        float h3v[4], h5v[4], h7v[4];
        {
            float p1, p2, p3;
            p1 = x3 + x5;  p2 = x2 + x6;  p3 = x1 + x7;
            h3v[0] = K3_0 * x4 + K3_1 * p1;
            h5v[0] = K5_0 * x4 + K5_1 * p1 + K5_2 * p2;
            h7v[0] = K7_0 * x4 + K7_1 * p1 + K7_2 * p2 + K7_3 * p3;
            p1 = x4 + x6;  p2 = x3 + x7;  p3 = x2 + x8;
            h3v[1] = K3_0 * x5 + K3_1 * p1;
            h5v[1] = K5_0 * x5 + K5_1 * p1 + K5_2 * p2;
            h7v[1] = K7_0 * x5 + K7_1 * p1 + K7_2 * p2 + K7_3 * p3;
            p1 = x5 + x7;  p2 = x4 + x8;  p3 = x3 + x9;
            h3v[2] = K3_0 * x6 + K3_1 * p1;
            h5v[2] = K5_0 * x6 + K5_1 * p1 + K5_2 * p2;
            h7v[2] = K7_0 * x6 + K7_1 * p1 + K7_2 * p2 + K7_3 * p3;
            p1 = x6 + x8;  p2 = x5 + x9;  p3 = x4 + x10;
            h3v[3] = K3_0 * x7 + K3_1 * p1;
            h5v[3] = K5_0 * x7 + K5_1 * p1 + K5_2 * p2;
            h7v[3] = K7_0 * x7 + K7_1 * p1 + K7_2 * p2 + K7_3 * p3;
        }
        ull t3a = pk2(h3v[0], h3v[1]), t3b = pk2(h3v[2], h3v[3]);
        ull t5a = pk2(h5v[0], h5v[1]), t5b = pk2(h5v[2], h5v[3]);
        ull t7a = pk2(h7v[0], h7v[1]), t7b = pk2(h7v[2], h7v[3]);
        ull rwa = pk2(x4, x5),          rwb = pk2(x6, x7);

        if (k <= 15) {                                   // d=0 init
            acc[k % 7][0] = mul2(a73, t7a);
            acc[k % 7][1] = mul2(a73, t7b);
        }
        if (k >= 1 && k <= 16) {                         // d=1
            ull u = acc[(k - 1) % 7][0], v = acc[(k - 1) % 7][1];
            u = fma2(a72, t7a, u);  v = fma2(a72, t7b, v);
            u = fma2(a52, t5a, u);  v = fma2(a52, t5b, v);
            acc[(k - 1) % 7][0] = u; acc[(k - 1) % 7][1] = v;
        }
        if (k >= 2 && k <= 17) {                         // d=2
            ull u = acc[(k - 2) % 7][0], v = acc[(k - 2) % 7][1];
            u = fma2(a71, t7a, u);  v = fma2(a71, t7b, v);
            u = fma2(a51, t5a, u);  v = fma2(a51, t5b, v);
            u = fma2(a31, t3a, u);  v = fma2(a31, t3b, v);
            acc[(k - 2) % 7][0] = u; acc[(k - 2) % 7][1] = v;
        }
        if (k >= 3 && k <= 18) {                         // d=3 (center)
            ull u = acc[(k - 3) % 7][0], v = acc[(k - 3) % 7][1];
            u = fma2(a70, t7a, u);  v = fma2(a70, t7b, v);
            u = fma2(a50, t5a, u);  v = fma2(a50, t5b, v);
            u = fma2(a30, t3a, u);  v = fma2(a30, t3b, v);
            u = fma2(cAp, rwa, u);  v = fma2(cAp, rwb, v);
            acc[(k - 3) % 7][0] = u; acc[(k - 3) % 7][1] = v;
        }
        if (k >= 4 && k <= 19) {                         // d=4
            ull u = acc[(k - 4) % 7][0], v = acc[(k - 4) % 7][1];
            u = fma2(a71, t7a, u);  v = fma2(a71, t7b, v);
            u = fma2(a51, t5a, u);  v = fma2(a51, t5b, v);
            u = fma2(a31, t3a, u);  v = fma2(a31, t3b, v);
            acc[(k - 4) % 7][0] = u; acc[(k - 4) % 7][1] = v;
        }
        if (k >= 5 && k <= 20) {                         // d=5
            ull u = acc[(k - 5) % 7][0], v = acc[(k - 5) % 7][1];
            u = fma2(a72, t7a, u);  v = fma2(a72, t7b, v);
            u = fma2(a52, t5a, u);  v = fma2(a52, t5b, v);
            acc[(k - 5) % 7][0] = u; acc[(k - 5) % 7][1] = v;
        }
        if (k >= 6) {                                    // d=6: finish + streaming STG.128
            ull ox = fma2(a73, t7a, acc[(k - 6) % 7][0]);
            ull oy = fma2(a73, t7b, acc[(k - 6) % 7][1]);
            asm volatile("st.global.cs.v2.u64 [%0], {%1, %2};"
                         :: "l"(orow + (size_t)(k - 6) * IMG), "l"(ox), "l"(oy)
                         : "memory");
        }
    }
}

// ---- TMA kernel: 128B-aligned quarter-split fill, per-warp waits ----
__global__ void __launch_bounds__(NTH, 3)
mgdf_tma_kernel(const __grid_constant__ CUtensorMap tmapA,   // box SW x 36
                const __grid_constant__ CUtensorMap tmapB,   // box SW x 26
                const float* __restrict__ w1p, const float* __restrict__ w2p,
                const float* __restrict__ w3p, const float* __restrict__ w4p,
                float* __restrict__ out)
{
    __shared__ __align__(128) float tile[SH][SW];
    __shared__ __align__(8) ull mbar[4];

    const int tid = threadIdx.x;
    const int wid = tid >> 5;           // == row-group
    const int tileX = blockIdx.x * TX;
    const int tileY = blockIdx.y * TY;
    const int img = blockIdx.z;
    float* op = out + (size_t)img * (IMG * IMG);

    const unsigned mb0 = smem_u32(&mbar[0]);
    if (tid < 4) {
        asm volatile("mbarrier.init.shared.b64 [%0], 1;"
                     :: "r"(mb0 + 8u * tid) : "memory");
    }
    __syncthreads();

    if (tid == 0) {
        // Quarters at rows {0,36,72,108}: offsets 0,36,72,108 * 544B all % 128 == 0
        const int rowoff[4] = {0, 36, 72, 108};
        #pragma unroll
        for (int q = 0; q < 4; q++) {
            unsigned mbx = mb0 + 8u * q;
            unsigned bytes = (q == 3) ? (unsigned)QBBYTES : (unsigned)QABYTES;
            const CUtensorMap* tm = (q == 3) ? &tmapB : &tmapA;
            asm volatile("mbarrier.arrive.expect_tx.shared.b64 _, [%0], %1;"
                         :: "r"(mbx), "r"(bytes) : "memory");
            asm volatile(
                "cp.async.bulk.tensor.3d.shared::cta.global.tile"
                ".mbarrier::complete_tx::bytes [%0], [%1, {%2, %3, %4}], [%5];"
                :: "r"(smem_u32(&tile[rowoff[q]][0])), "l"(tm),
                   "r"(tileX - 4), "r"(tileY - 3 + rowoff[q]), "r"(img), "r"(mbx)
                : "memory");
        }
    }

    // Per-warp waits: warp w streams rows w*16 .. w*16+21.
    // Q0: 0..35, Q1: 36..71, Q2: 72..107, Q3: 108..133
    if (wid <= 2)             mbar_wait(mb0,        0);   // w0,w1,w2
    if (wid >= 1 && wid <= 4) mbar_wait(mb0 + 8u,   0);   // w1..w4
    if (wid >= 4 && wid <= 6) mbar_wait(mb0 + 16u,  0);   // w4,w5,w6
    if (wid >= 6)             mbar_wait(mb0 + 24u,  0);   // w6,w7

    compute_tile(tile, w1p, w2p, w3p, w4p, op, tileX, tileY);
}

// ---- fallback kernel (TMA encode unavailable) ----
__global__ void __launch_bounds__(NTH, 3)
mgdf_ldg_kernel(const float* __restrict__ s,
                const float* __restrict__ w1p, const float* __restrict__ w2p,
                const float* __restrict__ w3p, const float* __restrict__ w4p,
                float* __restrict__ out)
{
    __shared__ __align__(16) float tile[SH][SW];

    const int img = blockIdx.z;
    const size_t base = (size_t)img * (IMG * IMG);
    const float* sp = s + base;
    float* op = out + base;
    const int tileX = blockIdx.x * TX;
    const int tileY = blockIdx.y * TY;
    const int tid = threadIdx.x;

    #pragma unroll
    for (int idx = tid; idx < SH * NF4; idx += NTH) {
        int r = idx / NF4;
        int c4 = idx - r * NF4;
        int gy = tileY - 3 + r;
        int gx = tileX - 4 + c4 * 4;
        float4 v = make_float4(0.f, 0.f, 0.f, 0.f);
        if ((unsigned)gy < (unsigned)IMG && (unsigned)gx < (unsigned)IMG)
            v = *reinterpret_cast<const float4*>(sp + gy * IMG + gx);
        *reinterpret_cast<float4*>(&tile[r][c4 * 4]) = v;
    }
    __syncthreads();

    compute_tile(tile, w1p, w2p, w3p, w4p, op, tileX, tileY);
}

typedef CUresult (*PFN_tmapEncode)(
    CUtensorMap*, CUtensorMapDataType, cuuint32_t, void*,
    const cuuint64_t*, const cuuint64_t*, const cuuint32_t*, const cuuint32_t*,
    CUtensorMapInterleave, CUtensorMapSwizzle, CUtensorMapL2promotion,
    CUtensorMapFloatOOBfill);

extern "C" void kernel_launch(void* const* d_in, const int* in_sizes, int n_in,
                              void* d_out, int out_size)
{
    const float* s  = (const float*)d_in[0];
    const float* w1 = (const float*)d_in[1];
    const float* w2 = (const float*)d_in[2];
    const float* w3 = (const float*)d_in[3];
    const float* w4 = (const float*)d_in[4];
    float* out = (float*)d_out;

    const int n_img = in_sizes[0] / (IMG * IMG);       // 192
    dim3 grid(IMG / TX, IMG / TY, n_img);              // (4, 4, 192)

    static PFN_tmapEncode pfn = nullptr;
    static bool resolved = false;
    if (!resolved) {
        void* fp = nullptr;
        cudaDriverEntryPointQueryResult qr = cudaDriverEntryPointSymbolNotFound;
        if (cudaGetDriverEntryPointByVersion("cuTensorMapEncodeTiled", &fp, 12000,
                                             cudaEnableDefault, &qr) == cudaSuccess &&
            qr == cudaDriverEntryPointSuccess)
            pfn = (PFN_tmapEncode)fp;
        resolved = true;
    }

    CUtensorMap tmapA, tmapB;
    bool use_tma = false;
    if (pfn) {
        cuuint64_t dims[3]    = {IMG, IMG, (cuuint64_t)n_img};
        cuuint64_t strides[2] = {IMG * 4ull, (cuuint64_t)IMG * IMG * 4ull};
        cuuint32_t boxA[3]    = {SW, QAROWS, 1};
        cuuint32_t boxB[3]    = {SW, QBROWS, 1};
        cuuint32_t estr[3]    = {1, 1, 1};
        bool okA = (pfn(&tmapA, CU_TENSOR_MAP_DATA_TYPE_FLOAT32, 3, (void*)s,
                        dims, strides, boxA, estr,
                        CU_TENSOR_MAP_INTERLEAVE_NONE, CU_TENSOR_MAP_SWIZZLE_NONE,
                        CU_TENSOR_MAP_L2_PROMOTION_L2_128B,
                        CU_TENSOR_MAP_FLOAT_OOB_FILL_NONE) == CUDA_SUCCESS);
        bool okB = (pfn(&tmapB, CU_TENSOR_MAP_DATA_TYPE_FLOAT32, 3, (void*)s,
                        dims, strides, boxB, estr,
                        CU_TENSOR_MAP_INTERLEAVE_NONE, CU_TENSOR_MAP_SWIZZLE_NONE,
                        CU_TENSOR_MAP_L2_PROMOTION_L2_128B,
                        CU_TENSOR_MAP_FLOAT_OOB_FILL_NONE) == CUDA_SUCCESS);
        use_tma = okA && okB;
    }

    if (use_tma)
        mgdf_tma_kernel<<<grid, NTH>>>(tmapA, tmapB, w1, w2, w3, w4, out);
    else
        mgdf_ldg_kernel<<<grid, NTH>>>(s, w1, w2, w3, w4, out);
}

// round 15
// speedup vs baseline: 1.1008x; 1.0010x over previous
#include <cuda_runtime.h>
#include <cuda.h>

typedef unsigned long long ull;

// out = (w1+w2)*s + (w3-w2)*G3(s) + (w4-w3)*G5(s) - w4*G7(s)
// Fine-grained tiling for DRAM duty cycle: tile 128x64 (38KB), NTH=128,
// 6 CTAs/SM (6 interleaved fill/compute phases per SM). TMA fill split into
// 5 slices (16/16/16/16/6 rows, all 128B-aligned offsets) with per-warp waits.
// Compute body identical to R10/R14: 4 cols/thread via 3x LDS.128, FFMA-imm
// horizontal, transposed-FIR f32x2 vertical ring, streaming stores.

#define IMG 512
#define TX 128
#define TY 64
#define NTH 128
#define SW 136            // TX + 8 (left halo 4, right halo 4)
#define SH 70             // TY + 6
#define NF4 (SW / 4)
#define STEPS 22
#define SAROWS 16         // slices 0..3
#define SBROWS 6          // slice 4
#define SABYTES (SAROWS * SW * 4)   // 8704
#define SBBYTES (SBROWS * SW * 4)   // 3264

#define K3_0 0.5220116f
#define K3_1 0.2389942f
#define K5_0 0.3695467f
#define K5_1 0.2444604f
#define K5_2 0.0707663f
#define K7_0 0.2880262f
#define K7_1 0.2231734f
#define K7_2 0.1038183f
#define K7_3 0.0289952f

__device__ __forceinline__ ull pk2(float lo, float hi) {
    ull r; asm("mov.b64 %0, {%1, %2};" : "=l"(r) : "f"(lo), "f"(hi)); return r;
}
__device__ __forceinline__ ull mul2(ull a, ull b) {
    ull r; asm("mul.rn.f32x2 %0, %1, %2;" : "=l"(r) : "l"(a), "l"(b)); return r;
}
__device__ __forceinline__ ull fma2(ull a, ull b, ull c) {
    ull r; asm("fma.rn.f32x2 %0, %1, %2, %3;" : "=l"(r) : "l"(a), "l"(b), "l"(c)); return r;
}
__device__ __forceinline__ unsigned smem_u32(const void* p) {
    unsigned r;
    asm("{ .reg .u64 t; cvta.to.shared.u64 t, %1; cvt.u32.u64 %0, t; }" : "=r"(r) : "l"(p));
    return r;
}
__device__ __forceinline__ void mbar_wait(unsigned mb, unsigned parity) {
    unsigned done;
    asm volatile(
        "{\n\t.reg .pred p;\n\t"
        "mbarrier.try_wait.parity.acquire.cta.shared::cta.b64 p, [%1], %2;\n\t"
        "selp.b32 %0, 1, 0, p;\n\t}"
        : "=r"(done) : "r"(mb), "r"(parity) : "memory");
    if (!done) {
        asm volatile(
            "{\n\t.reg .pred P1;\n\t"
            "W%=:\n\t"
            "mbarrier.try_wait.parity.acquire.cta.shared::cta.b64 P1, [%0], %1, 0x989680;\n\t"
            "@P1 bra.uni D%=;\n\t"
            "bra.uni W%=;\n\t"
            "D%=:\n\t}"
            :: "r"(mb), "r"(parity) : "memory");
    }
}

// ---- compute body: 4 cols/thread, 3x LDS.128 horizontal, f32x2 ring vertical ----
__device__ __forceinline__ void compute_tile(
    float (&tile)[SH][SW],
    const float* __restrict__ w1p, const float* __restrict__ w2p,
    const float* __restrict__ w3p, const float* __restrict__ w4p,
    float* __restrict__ op, int tileX, int tileY)
{
    const int tid = threadIdx.x;
    const float W1 = *w1p, W2 = *w2p, W3 = *w3p, W4 = *w4p;
    const float cA = W1 + W2, cB = W3 - W2, cC = W4 - W3, cD = -W4;
    const ull cAp = pk2(cA, cA);
    const ull a30 = pk2(cB * K3_0, cB * K3_0);
    const ull a31 = pk2(cB * K3_1, cB * K3_1);
    const ull a50 = pk2(cC * K5_0, cC * K5_0);
    const ull a51 = pk2(cC * K5_1, cC * K5_1);
    const ull a52 = pk2(cC * K5_2, cC * K5_2);
    const ull a70 = pk2(cD * K7_0, cD * K7_0);
    const ull a71 = pk2(cD * K7_1, cD * K7_1);
    const ull a72 = pk2(cD * K7_2, cD * K7_2);
    const ull a73 = pk2(cD * K7_3, cD * K7_3);

    const int xg = tid & 31;            // 32 col-groups of 4 cols
    const int rg = tid >> 5;            // 4 row-groups (== warp id)
    const int cb = 4 * xg;              // first float4; centers cb+4..cb+7
    const int rowBase = rg * 16;
    float* orow = op + (size_t)(tileY + rowBase) * IMG + tileX + 4 * xg;

    ull acc[7][2];

    #pragma unroll
    for (int k = 0; k < STEPS; k++) {
        const int sr = rowBase + k;

        float4 A = *reinterpret_cast<const float4*>(&tile[sr][cb]);
        float4 Bv = *reinterpret_cast<const float4*>(&tile[sr][cb + 4]);
        float4 C = *reinterpret_cast<const float4*>(&tile[sr][cb + 8]);
        float x1 = A.y, x2 = A.z, x3 = A.w;
        float x4 = Bv.x, x5 = Bv.y, x6 = Bv.z, x7 = Bv.w;
        float x8 = C.x, x9 = C.y, x10 = C.z;

        float h3v[4], h5v[4], h7v[4];
        {
            float p1, p2, p3;
            p1 = x3 + x5;  p2 = x2 + x6;  p3 = x1 + x7;
            h3v[0] = K3_0 * x4 + K3_1 * p1;
            h5v[0] = K5_0 * x4 + K5_1 * p1 + K5_2 * p2;
            h7v[0] = K7_0 * x4 + K7_1 * p1 + K7_2 * p2 + K7_3 * p3;
            p1 = x4 + x6;  p2 = x3 + x7;  p3 = x2 + x8;
            h3v[1] = K3_0 * x5 + K3_1 * p1;
            h5v[1] = K5_0 * x5 + K5_1 * p1 + K5_2 * p2;
            h7v[1] = K7_0 * x5 + K7_1 * p1 + K7_2 * p2 + K7_3 * p3;
            p1 = x5 + x7;  p2 = x4 + x8;  p3 = x3 + x9;
            h3v[2] = K3_0 * x6 + K3_1 * p1;
            h5v[2] = K5_0 * x6 + K5_1 * p1 + K5_2 * p2;
            h7v[2] = K7_0 * x6 + K7_1 * p1 + K7_2 * p2 + K7_3 * p3;
            p1 = x6 + x8;  p2 = x5 + x9;  p3 = x4 + x10;
            h3v[3] = K3_0 * x7 + K3_1 * p1;
            h5v[3] = K5_0 * x7 + K5_1 * p1 + K5_2 * p2;
            h7v[3] = K7_0 * x7 + K7_1 * p1 + K7_2 * p2 + K7_3 * p3;
        }
        ull t3a = pk2(h3v[0], h3v[1]), t3b = pk2(h3v[2], h3v[3]);
        ull t5a = pk2(h5v[0], h5v[1]), t5b = pk2(h5v[2], h5v[3]);
        ull t7a = pk2(h7v[0], h7v[1]), t7b = pk2(h7v[2], h7v[3]);
        ull rwa = pk2(x4, x5),          rwb = pk2(x6, x7);

        if (k <= 15) {                                   // d=0 init
            acc[k % 7][0] = mul2(a73, t7a);
            acc[k % 7][1] = mul2(a73, t7b);
        }
        if (k >= 1 && k <= 16) {                         // d=1
            ull u = acc[(k - 1) % 7][0], v = acc[(k - 1) % 7][1];
            u = fma2(a72, t7a, u);  v = fma2(a72, t7b, v);
            u = fma2(a52, t5a, u);  v = fma2(a52, t5b, v);
            acc[(k - 1) % 7][0] = u; acc[(k - 1) % 7][1] = v;
        }
        if (k >= 2 && k <= 17) {                         // d=2
            ull u = acc[(k - 2) % 7][0], v = acc[(k - 2) % 7][1];
            u = fma2(a71, t7a, u);  v = fma2(a71, t7b, v);
            u = fma2(a51, t5a, u);  v = fma2(a51, t5b, v);
            u = fma2(a31, t3a, u);  v = fma2(a31, t3b, v);
            acc[(k - 2) % 7][0] = u; acc[(k - 2) % 7][1] = v;
        }
        if (k >= 3 && k <= 18) {                         // d=3 (center)
            ull u = acc[(k - 3) % 7][0], v = acc[(k - 3) % 7][1];
            u = fma2(a70, t7a, u);  v = fma2(a70, t7b, v);
            u = fma2(a50, t5a, u);  v = fma2(a50, t5b, v);
            u = fma2(a30, t3a, u);  v = fma2(a30, t3b, v);
            u = fma2(cAp, rwa, u);  v = fma2(cAp, rwb, v);
            acc[(k - 3) % 7][0] = u; acc[(k - 3) % 7][1] = v;
        }
        if (k >= 4 && k <= 19) {                         // d=4
            ull u = acc[(k - 4) % 7][0], v = acc[(k - 4) % 7][1];
            u = fma2(a71, t7a, u);  v = fma2(a71, t7b, v);
            u = fma2(a51, t5a, u);  v = fma2(a51, t5b, v);
            u = fma2(a31, t3a, u);  v = fma2(a31, t3b, v);
            acc[(k - 4) % 7][0] = u; acc[(k - 4) % 7][1] = v;
        }
        if (k >= 5 && k <= 20) {                         // d=5
            ull u = acc[(k - 5) % 7][0], v = acc[(k - 5) % 7][1];
            u = fma2(a72, t7a, u);  v = fma2(a72, t7b, v);
            u = fma2(a52, t5a, u);  v = fma2(a52, t5b, v);
            acc[(k - 5) % 7][0] = u; acc[(k - 5) % 7][1] = v;
        }
        if (k >= 6) {                                    // d=6: finish + streaming STG.128
            ull ox = fma2(a73, t7a, acc[(k - 6) % 7][0]);
            ull oy = fma2(a73, t7b, acc[(k - 6) % 7][1]);
            asm volatile("st.global.cs.v2.u64 [%0], {%1, %2};"
                         :: "l"(orow + (size_t)(k - 6) * IMG), "l"(ox), "l"(oy)
                         : "memory");
        }
    }
}

// ---- TMA kernel: 5-slice fill (rows {0,16,32,48,64}), per-warp waits ----
__global__ void __launch_bounds__(NTH, 6)
mgdf_tma_kernel(const __grid_constant__ CUtensorMap tmapA,   // box SW x 16
                const __grid_constant__ CUtensorMap tmapB,   // box SW x 6
                const float* __restrict__ w1p, const float* __restrict__ w2p,
                const float* __restrict__ w3p, const float* __restrict__ w4p,
                float* __restrict__ out)
{
    __shared__ __align__(128) float tile[SH][SW];
    __shared__ __align__(8) ull mbar[5];

    const int tid = threadIdx.x;
    const int wid = tid >> 5;           // == row-group 0..3
    const int tileX = blockIdx.x * TX;
    const int tileY = blockIdx.y * TY;
    const int img = blockIdx.z;
    float* op = out + (size_t)img * (IMG * IMG);

    const unsigned mb0 = smem_u32(&mbar[0]);
    if (tid < 5) {
        asm volatile("mbarrier.init.shared.b64 [%0], 1;"
                     :: "r"(mb0 + 8u * tid) : "memory");
    }
    __syncthreads();

    if (tid == 0) {
        // Slices at rows {0,16,32,48,64}: offsets * 544B are all 128B-aligned
        // (row % 4 == 0 -> row*544 % 128 == 0). Heights 16,16,16,16,6.
        #pragma unroll
        for (int q = 0; q < 5; q++) {
            const int rowoff = q * 16;
            unsigned mbx = mb0 + 8u * q;
            unsigned bytes = (q == 4) ? (unsigned)SBBYTES : (unsigned)SABYTES;
            const CUtensorMap* tm = (q == 4) ? &tmapB : &tmapA;
            asm volatile("mbarrier.arrive.expect_tx.shared.b64 _, [%0], %1;"
                         :: "r"(mbx), "r"(bytes) : "memory");
            asm volatile(
                "cp.async.bulk.tensor.3d.shared::cta.global.tile"
                ".mbarrier::complete_tx::bytes [%0], [%1, {%2, %3, %4}], [%5];"
                :: "r"(smem_u32(&tile[rowoff][0])), "l"(tm),
                   "r"(tileX - 4), "r"(tileY - 3 + rowoff), "r"(img), "r"(mbx)
                : "memory");
        }
    }

    // Warp w streams rows w*16 .. w*16+21 -> needs slices w and w+1.
    mbar_wait(mb0 + 8u * wid,       0);
    mbar_wait(mb0 + 8u * (wid + 1), 0);

    compute_tile(tile, w1p, w2p, w3p, w4p, op, tileX, tileY);
}

// ---- fallback kernel (TMA encode unavailable) ----
__global__ void __launch_bounds__(NTH, 6)
mgdf_ldg_kernel(const float* __restrict__ s,
                const float* __restrict__ w1p, const float* __restrict__ w2p,
                const float* __restrict__ w3p, const float* __restrict__ w4p,
                float* __restrict__ out)
{
    __shared__ __align__(16) float tile[SH][SW];

    const int img = blockIdx.z;
    const size_t base = (size_t)img * (IMG * IMG);
    const float* sp = s + base;
    float* op = out + base;
    const int tileX = blockIdx.x * TX;
    const int tileY = blockIdx.y * TY;
    const int tid = threadIdx.x;

    #pragma unroll
    for (int idx = tid; idx < SH * NF4; idx += NTH) {
        int r = idx / NF4;
        int c4 = idx - r * NF4;
        int gy = tileY - 3 + r;
        int gx = tileX - 4 + c4 * 4;
        float4 v = make_float4(0.f, 0.f, 0.f, 0.f);
        if ((unsigned)gy < (unsigned)IMG && (unsigned)gx < (unsigned)IMG)
            v = *reinterpret_cast<const float4*>(sp + gy * IMG + gx);
        *reinterpret_cast<float4*>(&tile[r][c4 * 4]) = v;
    }
    __syncthreads();

    compute_tile(tile, w1p, w2p, w3p, w4p, op, tileX, tileY);
}

typedef CUresult (*PFN_tmapEncode)(
    CUtensorMap*, CUtensorMapDataType, cuuint32_t, void*,
    const cuuint64_t*, const cuuint64_t*, const cuuint32_t*, const cuuint32_t*,
    CUtensorMapInterleave, CUtensorMapSwizzle, CUtensorMapL2promotion,
    CUtensorMapFloatOOBfill);

extern "C" void kernel_launch(void* const* d_in, const int* in_sizes, int n_in,
                              void* d_out, int out_size)
{
    const float* s  = (const float*)d_in[0];
    const float* w1 = (const float*)d_in[1];
    const float* w2 = (const float*)d_in[2];
    const float* w3 = (const float*)d_in[3];
    const float* w4 = (const float*)d_in[4];
    float* out = (float*)d_out;

    const int n_img = in_sizes[0] / (IMG * IMG);       // 192
    dim3 grid(IMG / TX, IMG / TY, n_img);              // (4, 8, 192) = 6144

    static PFN_tmapEncode pfn = nullptr;
    static bool resolved = false;
    if (!resolved) {
        void* fp = nullptr;
        cudaDriverEntryPointQueryResult qr = cudaDriverEntryPointSymbolNotFound;
        if (cudaGetDriverEntryPointByVersion("cuTensorMapEncodeTiled", &fp, 12000,
                                             cudaEnableDefault, &qr) == cudaSuccess &&
            qr == cudaDriverEntryPointSuccess)
            pfn = (PFN_tmapEncode)fp;
        resolved = true;
    }

    CUtensorMap tmapA, tmapB;
    bool use_tma = false;
    if (pfn) {
        cuuint64_t dims[3]    = {IMG, IMG, (cuuint64_t)n_img};
        cuuint64_t strides[2] = {IMG * 4ull, (cuuint64_t)IMG * IMG * 4ull};
        cuuint32_t boxA[3]    = {SW, SAROWS, 1};
        cuuint32_t boxB[3]    = {SW, SBROWS, 1};
        cuuint32_t estr[3]    = {1, 1, 1};
        bool okA = (pfn(&tmapA, CU_TENSOR_MAP_DATA_TYPE_FLOAT32, 3, (void*)s,
                        dims, strides, boxA, estr,
                        CU_TENSOR_MAP_INTERLEAVE_NONE, CU_TENSOR_MAP_SWIZZLE_NONE,
                        CU_TENSOR_MAP_L2_PROMOTION_L2_128B,
                        CU_TENSOR_MAP_FLOAT_OOB_FILL_NONE) == CUDA_SUCCESS);
        bool okB = (pfn(&tmapB, CU_TENSOR_MAP_DATA_TYPE_FLOAT32, 3, (void*)s,
                        dims, strides, boxB, estr,
                        CU_TENSOR_MAP_INTERLEAVE_NONE, CU_TENSOR_MAP_SWIZZLE_NONE,
                        CU_TENSOR_MAP_L2_PROMOTION_L2_128B,
                        CU_TENSOR_MAP_FLOAT_OOB_FILL_NONE) == CUDA_SUCCESS);
        use_tma = okA && okB;
    }

    if (use_tma)
        mgdf_tma_kernel<<<grid, NTH>>>(tmapA, tmapB, w1, w2, w3, w4, out);
    else
        mgdf_ldg_kernel<<<grid, NTH>>>(s, w1, w2, w3, w4, out);
}